// round 10
// baseline (speedup 1.0000x reference)
#include <cuda_runtime.h>
#include <cuda_bf16.h>
#include <cuda_fp16.h>
#include <cstdint>

// Problem constants
#define E1C   600000
#define E2C   300000
#define N1C   100000
#define N2C   20000
#define NSRC0 400000

// ---------------- scratch (device globals; no allocation allowed) ----------------
__device__ int    g_rowptr1[N1C + 1];
__device__ int    g_cursor1[N1C + 1];
__device__ int    g_rowptr2[N2C + 1];
__device__ int    g_cursor2[N2C + 1];
__device__ int    g_end1[E1C];          // packed sorted: gather index (into xg)
__device__ float4 g_ew1[E1C];           // packed sorted: comp[et]*norm per basis
__device__ int    g_end2[E2C];
__device__ float4 g_ew2[E2C];
__device__ __half g_xg[(size_t)NSRC0 * 64];  // 51.2 MB fp16 gathered emb (L2-resident)
__device__ __half g_z1[(size_t)N1C * 256];   // 51.2 MB (fp16)
__device__ float  g_h [(size_t)N1C * 64];    // 25.6 MB
__device__ __half g_z2[(size_t)N2C * 256];   // 10.2 MB (fp16)

// ---------------- MMA helpers ----------------
__device__ __forceinline__ uint32_t smem_u32(const void* p) {
    return (uint32_t)__cvta_generic_to_shared(p);
}

__device__ __forceinline__ void ldsm_x4(uint32_t& r0, uint32_t& r1, uint32_t& r2, uint32_t& r3,
                                        uint32_t addr) {
    asm volatile("ldmatrix.sync.aligned.m8n8.x4.shared.b16 {%0,%1,%2,%3}, [%4];"
                 : "=r"(r0), "=r"(r1), "=r"(r2), "=r"(r3) : "r"(addr));
}

__device__ __forceinline__ void ldsm_x4_t(uint32_t& r0, uint32_t& r1, uint32_t& r2, uint32_t& r3,
                                          uint32_t addr) {
    asm volatile("ldmatrix.sync.aligned.m8n8.x4.trans.shared.b16 {%0,%1,%2,%3}, [%4];"
                 : "=r"(r0), "=r"(r1), "=r"(r2), "=r"(r3) : "r"(addr));
}

__device__ __forceinline__ void mma16816(float* c,
                                         uint32_t a0, uint32_t a1, uint32_t a2, uint32_t a3,
                                         uint32_t b0, uint32_t b1) {
    asm volatile("mma.sync.aligned.m16n8k16.row.col.f32.f16.f16.f32 "
                 "{%0,%1,%2,%3}, {%4,%5,%6,%7}, {%8,%9}, {%0,%1,%2,%3};"
                 : "+f"(c[0]), "+f"(c[1]), "+f"(c[2]), "+f"(c[3])
                 : "r"(a0), "r"(a1), "r"(a2), "r"(a3), "r"(b0), "r"(b1));
}

// ---------------- counting-sort kernels ----------------
__global__ void k_zero(int* __restrict__ c1, int n1, int* __restrict__ c2, int n2) {
    int i = blockIdx.x * blockDim.x + threadIdx.x;
    if (i <= n1) c1[i] = 0;
    if (i <= n2) c2[i] = 0;
}

__global__ void k_hist(const int* __restrict__ dst1, const int* __restrict__ dst2,
                       int* __restrict__ c1, int* __restrict__ c2) {
    int i = blockIdx.x * blockDim.x + threadIdx.x;
    if (i < E1C) {
        atomicAdd(&c1[__ldg(dst1 + i)], 1);
    } else if (i < E1C + E2C) {
        atomicAdd(&c2[__ldg(dst2 + i - E1C)], 1);
    }
}

// single-block fused exclusive scan for both count arrays (1024 threads)
__device__ __forceinline__ void scan_one(const int* __restrict__ cnt,
                                         int* __restrict__ rp, int* __restrict__ cur,
                                         int n, int total, int* ws) {
    const int t = threadIdx.x;
    const int chunk = (n + 1023) >> 10;
    const int s = t * chunk;
    const int e = (s + chunk < n) ? s + chunk : n;
    int sum = 0;
    for (int i = s; i < e; i++) sum += __ldg(cnt + i);
    int lane = t & 31, wid = t >> 5;
    int v = sum;
#pragma unroll
    for (int o = 1; o < 32; o <<= 1) {
        int y = __shfl_up_sync(0xffffffffu, v, o);
        if (lane >= o) v += y;
    }
    if (lane == 31) ws[wid] = v;
    __syncthreads();
    if (wid == 0) {
        int w = ws[lane];
#pragma unroll
        for (int o = 1; o < 32; o <<= 1) {
            int y = __shfl_up_sync(0xffffffffu, w, o);
            if (lane >= o) w += y;
        }
        ws[lane] = w;
    }
    __syncthreads();
    int run = v - sum + (wid ? ws[wid - 1] : 0);
    for (int i = s; i < e; i++) {
        int c = __ldg(cnt + i);
        rp[i] = run;
        cur[i] = run;
        run += c;
    }
    if (t == 0) rp[n] = total;
}

__global__ __launch_bounds__(1024)
void k_scan_fused(const int* __restrict__ cnt1, int* __restrict__ rp1, int* __restrict__ cur1,
                  const int* __restrict__ cnt2, int* __restrict__ rp2, int* __restrict__ cur2) {
    __shared__ int ws[32];
    scan_one(cnt1, rp1, cur1, N1C, E1C, ws);
    __syncthreads();
    scan_one(cnt2, rp2, cur2, N2C, E2C, ws);
}

// scatter + pack: write sorted edge records {gather_index, comp[et]*norm}
__global__ void k_scatter_pack(
    const int* __restrict__ dst1, const int* __restrict__ src1,
    const int* __restrict__ et1, const float* __restrict__ nrm1,
    const float4* __restrict__ comp1,
    int* __restrict__ cur1, int* __restrict__ end1, float4* __restrict__ ew1,
    const int* __restrict__ dst2, const int* __restrict__ src2,
    const int* __restrict__ et2, const float* __restrict__ nrm2,
    const float4* __restrict__ comp2,
    int* __restrict__ cur2, int* __restrict__ end2, float4* __restrict__ ew2) {
    int i = blockIdx.x * blockDim.x + threadIdx.x;
    if (i < E1C) {
        int p = atomicAdd(&cur1[__ldg(dst1 + i)], 1);
        float n = __ldg(nrm1 + i);
        float4 c = __ldg(comp1 + __ldg(et1 + i));
        end1[p] = __ldg(src1 + i);      // direct index into xg
        ew1[p] = make_float4(c.x * n, c.y * n, c.z * n, c.w * n);
    } else if (i < E1C + E2C) {
        int e = i - E1C;
        int p = atomicAdd(&cur2[__ldg(dst2 + e)], 1);
        float n = __ldg(nrm2 + e);
        float4 c = __ldg(comp2 + __ldg(et2 + e));
        end2[p] = __ldg(src2 + e);
        ew2[p] = make_float4(c.x * n, c.y * n, c.z * n, c.w * n);
    }
}

// materialize xg = fp16(emb[input_nodes]); one warp per row, coalesced write
__global__ void k_gather_x(const int* __restrict__ inodes, const float* __restrict__ emb,
                           __half* __restrict__ xg) {
    int w = (blockIdx.x * blockDim.x + threadIdx.x) >> 5;
    int lane = threadIdx.x & 31;
    if (w >= NSRC0) return;
    int nd = __ldg(inodes + w);
    float2 v = __ldg((const float2*)(emb + (size_t)nd * 64) + lane);
    ((__half2*)(xg + (size_t)w * 64))[lane] = __float22half2_rn(v);
}

// ---------------- per-dst basis aggregation (one warp per dst, full occupancy) ----------------
// z[dst, b*64 + d] = sum_e ew_e[b] * x[end_e, d]; fp32 accumulate, fp16 store.
// XHALF selects fp16 (xg) vs fp32 (h) source rows.
template <bool XHALF>
__device__ __forceinline__ float2 ldx(const void* x, int nd, int lane) {
    if (XHALF) {
        __half2 hv = __ldg((const __half2*)((const __half*)x + (size_t)nd * 64) + lane);
        return __half22float2(hv);
    } else {
        return __ldg((const float2*)((const float*)x + (size_t)nd * 64) + lane);
    }
}

template <bool XHALF>
__global__ void k_agg(const int* __restrict__ rowptr, const int* __restrict__ end,
                      const float4* __restrict__ ew, const void* __restrict__ x,
                      __half* __restrict__ zout, int ndst) {
    int gw = (blockIdx.x * blockDim.x + threadIdx.x) >> 5;
    int lane = threadIdx.x & 31;
    if (gw >= ndst) return;

    float2 a0 = {0.f, 0.f}, a1 = {0.f, 0.f}, a2 = {0.f, 0.f}, a3 = {0.f, 0.f};
    int p = __ldg(rowptr + gw);
    const int pe = __ldg(rowptr + gw + 1);

    for (; p + 4 <= pe; p += 4) {
        int n0 = __ldg(end + p), n1 = __ldg(end + p + 1);
        int n2 = __ldg(end + p + 2), n3 = __ldg(end + p + 3);
        float4 w0 = __ldg(ew + p), w1 = __ldg(ew + p + 1);
        float4 w2 = __ldg(ew + p + 2), w3 = __ldg(ew + p + 3);
        float2 x0 = ldx<XHALF>(x, n0, lane);
        float2 x1 = ldx<XHALF>(x, n1, lane);
        float2 x2 = ldx<XHALF>(x, n2, lane);
        float2 x3 = ldx<XHALF>(x, n3, lane);
        a0.x = fmaf(w0.x, x0.x, a0.x); a0.y = fmaf(w0.x, x0.y, a0.y);
        a1.x = fmaf(w0.y, x0.x, a1.x); a1.y = fmaf(w0.y, x0.y, a1.y);
        a2.x = fmaf(w0.z, x0.x, a2.x); a2.y = fmaf(w0.z, x0.y, a2.y);
        a3.x = fmaf(w0.w, x0.x, a3.x); a3.y = fmaf(w0.w, x0.y, a3.y);
        a0.x = fmaf(w1.x, x1.x, a0.x); a0.y = fmaf(w1.x, x1.y, a0.y);
        a1.x = fmaf(w1.y, x1.x, a1.x); a1.y = fmaf(w1.y, x1.y, a1.y);
        a2.x = fmaf(w1.z, x1.x, a2.x); a2.y = fmaf(w1.z, x1.y, a2.y);
        a3.x = fmaf(w1.w, x1.x, a3.x); a3.y = fmaf(w1.w, x1.y, a3.y);
        a0.x = fmaf(w2.x, x2.x, a0.x); a0.y = fmaf(w2.x, x2.y, a0.y);
        a1.x = fmaf(w2.y, x2.x, a1.x); a1.y = fmaf(w2.y, x2.y, a1.y);
        a2.x = fmaf(w2.z, x2.x, a2.x); a2.y = fmaf(w2.z, x2.y, a2.y);
        a3.x = fmaf(w2.w, x2.x, a3.x); a3.y = fmaf(w2.w, x2.y, a3.y);
        a0.x = fmaf(w3.x, x3.x, a0.x); a0.y = fmaf(w3.x, x3.y, a0.y);
        a1.x = fmaf(w3.y, x3.x, a1.x); a1.y = fmaf(w3.y, x3.y, a1.y);
        a2.x = fmaf(w3.z, x3.x, a2.x); a2.y = fmaf(w3.z, x3.y, a2.y);
        a3.x = fmaf(w3.w, x3.x, a3.x); a3.y = fmaf(w3.w, x3.y, a3.y);
    }
    for (; p < pe; p++) {
        int n0 = __ldg(end + p);
        float4 w0 = __ldg(ew + p);
        float2 x0 = ldx<XHALF>(x, n0, lane);
        a0.x = fmaf(w0.x, x0.x, a0.x); a0.y = fmaf(w0.x, x0.y, a0.y);
        a1.x = fmaf(w0.y, x0.x, a1.x); a1.y = fmaf(w0.y, x0.y, a1.y);
        a2.x = fmaf(w0.z, x0.x, a2.x); a2.y = fmaf(w0.z, x0.y, a2.y);
        a3.x = fmaf(w0.w, x0.x, a3.x); a3.y = fmaf(w0.w, x0.y, a3.y);
    }
    __half2* zr = (__half2*)(zout + (size_t)gw * 256);   // k = b*64+d (b-major = V flat)
    zr[lane]      = __float22half2_rn(a0);
    zr[32 + lane] = __float22half2_rn(a1);
    zr[64 + lane] = __float22half2_rn(a2);
    zr[96 + lane] = __float22half2_rn(a3);
}

// ---------------- HMMA projection GEMM: C[n,OUTD] = Z[n,256] @ W[256,OUTD] + bias ----------------
template <int OUTD, bool RELU>
__global__ __launch_bounds__(256)
void k_hgemm(const __half* __restrict__ Z, const float* __restrict__ W,
             const float* __restrict__ bias, float* __restrict__ C, int nrows) {
    constexpr int LDA = 264;                     // halves
    constexpr int LDB = (OUTD == 64) ? 72 : 40;  // halves
    constexpr int NT = OUTD / 8;                 // n-tiles per warp strip

    extern __shared__ __half sh[];
    __half* As = sh;                  // [128][LDA]
    __half* Bs = sh + 128 * LDA;      // [256][LDB]

    const int t = threadIdx.x;
    const int warp = t >> 5, lane = t & 31;
    const int rowbase = blockIdx.x * 128;

    // stage Z tile (128 x 256 halves, 16B chunks)
    for (int i = t; i < 128 * 32; i += 256) {
        int row = i >> 5, ch = i & 31;
        int gr = rowbase + row;
        float4 v = make_float4(0.f, 0.f, 0.f, 0.f);
        if (gr < nrows) v = *(const float4*)(Z + (size_t)gr * 256 + ch * 8);
        *(float4*)(As + row * LDA + ch * 8) = v;
    }
    // stage W converted to fp16 (256 x OUTD)
    for (int i = t; i < 256 * OUTD / 4; i += 256) {
        int k = i / (OUTD / 4), c4 = i % (OUTD / 4);
        float4 v = *(const float4*)(W + k * OUTD + c4 * 4);
        __half2* d = (__half2*)(Bs + k * LDB + c4 * 4);
        d[0] = __floats2half2_rn(v.x, v.y);
        d[1] = __floats2half2_rn(v.z, v.w);
    }
    __syncthreads();

    float acc[NT][4];
#pragma unroll
    for (int j = 0; j < NT; j++)
#pragma unroll
        for (int c = 0; c < 4; c++) acc[j][c] = 0.f;

    const int wm = warp * 16;
    const uint32_t As32 = smem_u32(As);
    const uint32_t Bs32 = smem_u32(Bs);
    const int arow = wm + (lane & 7) + ((lane >> 3) & 1) * 8;
    const int acol8 = (lane >> 4) * 8;
    const int brow_off = (lane & 7) + ((lane >> 3) & 1) * 8;
    const int bcol8 = (lane >> 4) * 8;

#pragma unroll 4
    for (int kk = 0; kk < 16; kk++) {
        const int k0 = kk * 16;
        uint32_t a0, a1, a2, a3;
        ldsm_x4(a0, a1, a2, a3, As32 + (arow * LDA + k0 + acol8) * 2);
#pragma unroll
        for (int j = 0; j < NT / 2; j++) {
            const int nb0 = j * 16;
            uint32_t b0, b1, b2, b3;
            ldsm_x4_t(b0, b1, b2, b3,
                      Bs32 + ((k0 + brow_off) * LDB + nb0 + bcol8) * 2);
            mma16816(acc[2 * j],     a0, a1, a2, a3, b0, b1);
            mma16816(acc[2 * j + 1], a0, a1, a2, a3, b2, b3);
        }
    }

    // epilogue: bias (+ReLU), direct gmem float2 stores
    const int r0 = rowbase + wm + lane / 4;
    const int r1 = r0 + 8;
#pragma unroll
    for (int j = 0; j < NT; j++) {
        int nc = j * 8 + (lane % 4) * 2;
        float2 bv = __ldg((const float2*)(bias + nc));
        float2 o0 = make_float2(acc[j][0] + bv.x, acc[j][1] + bv.y);
        float2 o1 = make_float2(acc[j][2] + bv.x, acc[j][3] + bv.y);
        if (RELU) {
            o0.x = fmaxf(o0.x, 0.f); o0.y = fmaxf(o0.y, 0.f);
            o1.x = fmaxf(o1.x, 0.f); o1.y = fmaxf(o1.y, 0.f);
        }
        if (r0 < nrows) *(float2*)(C + (size_t)r0 * OUTD + nc) = o0;
        if (r1 < nrows) *(float2*)(C + (size_t)r1 * OUTD + nc) = o1;
    }
}

// ---------------- host launcher ----------------
extern "C" void kernel_launch(void* const* d_in, const int* in_sizes, int n_in,
                              void* d_out, int out_size) {
    const int*   input_nodes = (const int*)d_in[0];
    const int*   src1  = (const int*)d_in[1];
    const int*   dst1  = (const int*)d_in[2];
    const int*   etyp1 = (const int*)d_in[3];
    const float* norm1 = (const float*)d_in[4];
    const int*   src2  = (const int*)d_in[5];
    const int*   dst2  = (const int*)d_in[6];
    const int*   etyp2 = (const int*)d_in[7];
    const float* norm2 = (const float*)d_in[8];
    const float* emb   = (const float*)d_in[9];
    const float* V1    = (const float*)d_in[10];
    const float* comp1 = (const float*)d_in[11];
    const float* b1    = (const float*)d_in[12];
    const float* V2    = (const float*)d_in[13];
    const float* comp2 = (const float*)d_in[14];
    const float* b2    = (const float*)d_in[15];
    float* out = (float*)d_out;

    void* p;
    int *rowptr1, *cursor1, *rowptr2, *cursor2, *end1, *end2;
    float4 *ew1, *ew2;
    __half *xg, *z1, *z2;
    float *h;
    cudaGetSymbolAddress(&p, g_rowptr1); rowptr1 = (int*)p;
    cudaGetSymbolAddress(&p, g_cursor1); cursor1 = (int*)p;
    cudaGetSymbolAddress(&p, g_rowptr2); rowptr2 = (int*)p;
    cudaGetSymbolAddress(&p, g_cursor2); cursor2 = (int*)p;
    cudaGetSymbolAddress(&p, g_end1);    end1    = (int*)p;
    cudaGetSymbolAddress(&p, g_ew1);     ew1     = (float4*)p;
    cudaGetSymbolAddress(&p, g_end2);    end2    = (int*)p;
    cudaGetSymbolAddress(&p, g_ew2);     ew2     = (float4*)p;
    cudaGetSymbolAddress(&p, g_xg);      xg      = (__half*)p;
    cudaGetSymbolAddress(&p, g_z1);      z1      = (__half*)p;
    cudaGetSymbolAddress(&p, g_h);       h       = (float*)p;
    cudaGetSymbolAddress(&p, g_z2);      z2      = (__half*)p;

    const int smem1 = (128 * 264 + 256 * 72) * 2;   // 104448 B
    const int smem2 = (128 * 264 + 256 * 40) * 2;   //  88064 B
    cudaFuncSetAttribute(k_hgemm<64, true>,  cudaFuncAttributeMaxDynamicSharedMemorySize, smem1);
    cudaFuncSetAttribute(k_hgemm<32, false>, cudaFuncAttributeMaxDynamicSharedMemorySize, smem2);

    // --- materialize fp16 gathered features (independent of sort chain) ---
    k_gather_x<<<(NSRC0 * 32 + 255) / 256, 256>>>(input_nodes, emb, xg);

    // --- counting sort by dst + edge packing (both layers) ---
    k_zero<<<(N1C + 256) / 256, 256>>>(cursor1, N1C, cursor2, N2C);
    k_hist<<<(E1C + E2C + 255) / 256, 256>>>(dst1, dst2, cursor1, cursor2);
    k_scan_fused<<<1, 1024>>>(cursor1, rowptr1, cursor1, cursor2, rowptr2, cursor2);
    k_scatter_pack<<<(E1C + E2C + 255) / 256, 256>>>(
        dst1, src1, etyp1, norm1, (const float4*)comp1,
        cursor1, end1, ew1,
        dst2, src2, etyp2, norm2, (const float4*)comp2,
        cursor2, end2, ew2);

    // --- layer 1: aggregate (fp16 L2-resident gathers) -> project (HMMA) ---
    k_agg<true><<<(N1C * 32 + 255) / 256, 256>>>(rowptr1, end1, ew1, xg, z1, N1C);
    k_hgemm<64, true><<<(N1C + 127) / 128, 256, smem1>>>(z1, V1, b1, h, N1C);

    // --- layer 2 ---
    k_agg<false><<<(N2C * 32 + 255) / 256, 256>>>(rowptr2, end2, ew2, h, z2, N2C);
    k_hgemm<32, false><<<(N2C + 127) / 128, 256, smem2>>>(z2, V2, b2, out, N2C);
}

// round 11
// speedup vs baseline: 2.3191x; 2.3191x over previous
#include <cuda_runtime.h>
#include <cuda_bf16.h>
#include <cuda_fp16.h>
#include <cstdint>

// Problem constants
#define E1C   600000
#define E2C   300000
#define N1C   100000
#define N2C   20000

// ---------------- scratch (device globals; no allocation allowed) ----------------
__device__ int    g_rowptr1[N1C + 1];
__device__ int    g_cursor1[N1C + 1];
__device__ int    g_rowptr2[N2C + 1];
__device__ int    g_cursor2[N2C + 1];
__device__ int    g_bs1[64];
__device__ int    g_bs2[64];
__device__ int    g_end1[E1C];          // packed sorted: gather index
__device__ float4 g_ew1[E1C];           // packed sorted: comp[et]*norm per basis
__device__ int    g_end2[E2C];
__device__ float4 g_ew2[E2C];
__device__ __half g_z1[(size_t)N1C * 256];   // 51.2 MB (fp16)
__device__ __half g_h [(size_t)N1C * 64];    // 12.8 MB (fp16, L2-resident)
__device__ __half g_z2[(size_t)N2C * 256];   // 10.2 MB (fp16)

// ---------------- MMA helpers ----------------
__device__ __forceinline__ uint32_t smem_u32(const void* p) {
    return (uint32_t)__cvta_generic_to_shared(p);
}

__device__ __forceinline__ void ldsm_x4(uint32_t& r0, uint32_t& r1, uint32_t& r2, uint32_t& r3,
                                        uint32_t addr) {
    asm volatile("ldmatrix.sync.aligned.m8n8.x4.shared.b16 {%0,%1,%2,%3}, [%4];"
                 : "=r"(r0), "=r"(r1), "=r"(r2), "=r"(r3) : "r"(addr));
}

__device__ __forceinline__ void ldsm_x4_t(uint32_t& r0, uint32_t& r1, uint32_t& r2, uint32_t& r3,
                                          uint32_t addr) {
    asm volatile("ldmatrix.sync.aligned.m8n8.x4.trans.shared.b16 {%0,%1,%2,%3}, [%4];"
                 : "=r"(r0), "=r"(r1), "=r"(r2), "=r"(r3) : "r"(addr));
}

__device__ __forceinline__ void mma16816(float* c,
                                         uint32_t a0, uint32_t a1, uint32_t a2, uint32_t a3,
                                         uint32_t b0, uint32_t b1) {
    asm volatile("mma.sync.aligned.m16n8k16.row.col.f32.f16.f16.f32 "
                 "{%0,%1,%2,%3}, {%4,%5,%6,%7}, {%8,%9}, {%0,%1,%2,%3};"
                 : "+f"(c[0]), "+f"(c[1]), "+f"(c[2]), "+f"(c[3])
                 : "r"(a0), "r"(a1), "r"(a2), "r"(a3), "r"(b0), "r"(b1));
}

// ---------------- counting-sort kernels ----------------
__global__ void k_zero(int* __restrict__ c1, int n1, int* __restrict__ c2, int n2) {
    int i = blockIdx.x * blockDim.x + threadIdx.x;
    if (i <= n1) c1[i] = 0;
    if (i <= n2) c2[i] = 0;
}

__global__ void k_hist(const int* __restrict__ dst1, const int* __restrict__ dst2,
                       int* __restrict__ c1, int* __restrict__ c2) {
    int i = blockIdx.x * blockDim.x + threadIdx.x;
    if (i < E1C) {
        atomicAdd(&c1[__ldg(dst1 + i)], 1);
    } else if (i < E1C + E2C) {
        atomicAdd(&c2[__ldg(dst2 + i - E1C)], 1);
    }
}

// per-block exclusive scan over 2048-element chunks; both layers in one launch
__global__ void k_scan_local2(const int* __restrict__ cntA, int* __restrict__ exclA,
                              int* __restrict__ bsA, int nA, int nbA,
                              const int* __restrict__ cntB, int* __restrict__ exclB,
                              int* __restrict__ bsB, int nB) {
    const int t = threadIdx.x;
    const bool isA = (blockIdx.x < (unsigned)nbA);
    const int bid = isA ? blockIdx.x : blockIdx.x - nbA;
    const int* cnt = isA ? cntA : cntB;
    int* excl = isA ? exclA : exclB;
    int* bsums = isA ? bsA : bsB;
    const int n = isA ? nA : nB;

    const int base = bid * 2048 + t * 8;
    int v[8], pre[8], s = 0;
#pragma unroll
    for (int j = 0; j < 8; j++) {
        int idx = base + j;
        v[j] = (idx < n) ? cnt[idx] : 0;
        pre[j] = s;
        s += v[j];
    }
    int lane = t & 31, wid = t >> 5;
    int inc = s;
#pragma unroll
    for (int off = 1; off < 32; off <<= 1) {
        int y = __shfl_up_sync(0xffffffffu, inc, off);
        if (lane >= off) inc += y;
    }
    __shared__ int wsum[8];
    __shared__ int wexcl[8];
    if (lane == 31) wsum[wid] = inc;
    __syncthreads();
    if (t == 0) {
        int run = 0;
        for (int w = 0; w < 8; w++) { wexcl[w] = run; run += wsum[w]; }
    }
    __syncthreads();
    int texcl = wexcl[wid] + inc - s;
#pragma unroll
    for (int j = 0; j < 8; j++) {
        int idx = base + j;
        if (idx < n) excl[idx] = texcl + pre[j];
    }
    if (t == 255) bsums[bid] = wexcl[7] + wsum[7];
}

// one block scans each bsums array (<=64 entries)
__global__ void k_scan_bsums2(int* __restrict__ bsA, int nA,
                              int* __restrict__ bsB, int nB) {
    __shared__ int sh[64];
    int t = threadIdx.x;
    int* bs = (blockIdx.x == 0) ? bsA : bsB;
    int nb  = (blockIdx.x == 0) ? nA : nB;
    int v = (t < nb) ? bs[t] : 0;
    int x = v;
    sh[t] = x;
    __syncthreads();
    for (int off = 1; off < 64; off <<= 1) {
        int y = (t >= off) ? sh[t - off] : 0;
        __syncthreads();
        x += y;
        sh[t] = x;
        __syncthreads();
    }
    if (t < nb) bs[t] = x - v;   // exclusive
}

__global__ void k_scan_add2(int* __restrict__ rpA, int* __restrict__ curA,
                            const int* __restrict__ bsA, int nA, int totA, int gA,
                            int* __restrict__ rpB, int* __restrict__ curB,
                            const int* __restrict__ bsB, int nB, int totB) {
    const bool isA = (blockIdx.x < (unsigned)gA);
    const int bid = isA ? blockIdx.x : blockIdx.x - gA;
    int* rowptr = isA ? rpA : rpB;
    int* cursor = isA ? curA : curB;
    const int* bsums = isA ? bsA : bsB;
    const int n = isA ? nA : nB;
    const int total = isA ? totA : totB;
    int i = bid * blockDim.x + threadIdx.x;
    if (i < n) {
        int f = rowptr[i] + bsums[i >> 11];
        rowptr[i] = f;
        cursor[i] = f;
    }
    if (i == 0) rowptr[n] = total;
}

// scatter + pack: write sorted edge records {gather_index, comp[et]*norm}
__global__ void k_scatter_pack(
    const int* __restrict__ dst1, const int* __restrict__ src1,
    const int* __restrict__ et1, const float* __restrict__ nrm1,
    const int* __restrict__ inodes, const float4* __restrict__ comp1,
    int* __restrict__ cur1, int* __restrict__ end1, float4* __restrict__ ew1,
    const int* __restrict__ dst2, const int* __restrict__ src2,
    const int* __restrict__ et2, const float* __restrict__ nrm2,
    const float4* __restrict__ comp2,
    int* __restrict__ cur2, int* __restrict__ end2, float4* __restrict__ ew2) {
    int i = blockIdx.x * blockDim.x + threadIdx.x;
    if (i < E1C) {
        int p = atomicAdd(&cur1[__ldg(dst1 + i)], 1);
        int nd = __ldg(inodes + __ldg(src1 + i));
        float n = __ldg(nrm1 + i);
        float4 c = __ldg(comp1 + __ldg(et1 + i));
        end1[p] = nd;
        ew1[p] = make_float4(c.x * n, c.y * n, c.z * n, c.w * n);
    } else if (i < E1C + E2C) {
        int e = i - E1C;
        int p = atomicAdd(&cur2[__ldg(dst2 + e)], 1);
        int nd = __ldg(src2 + e);
        float n = __ldg(nrm2 + e);
        float4 c = __ldg(comp2 + __ldg(et2 + e));
        end2[p] = nd;
        ew2[p] = make_float4(c.x * n, c.y * n, c.z * n, c.w * n);
    }
}

// ---------------- per-dst basis aggregation (one warp per dst, full occupancy) ----------------
// z[dst, b*64 + d] = sum_e ew_e[b] * x[end_e, d]; fp32 accumulate, fp16 store.
// XHALF selects fp16 (h) vs fp32 (emb) source rows.
template <bool XHALF>
__device__ __forceinline__ float2 ldx(const void* x, int nd, int lane) {
    if (XHALF) {
        __half2 hv = __ldg((const __half2*)((const __half*)x + (size_t)nd * 64) + lane);
        return __half22float2(hv);
    } else {
        return __ldg((const float2*)((const float*)x + (size_t)nd * 64) + lane);
    }
}

template <bool XHALF>
__global__ void k_agg(const int* __restrict__ rowptr, const int* __restrict__ end,
                      const float4* __restrict__ ew, const void* __restrict__ x,
                      __half* __restrict__ zout, int ndst) {
    int gw = (blockIdx.x * blockDim.x + threadIdx.x) >> 5;
    int lane = threadIdx.x & 31;
    if (gw >= ndst) return;

    float2 a0 = {0.f, 0.f}, a1 = {0.f, 0.f}, a2 = {0.f, 0.f}, a3 = {0.f, 0.f};
    int p = __ldg(rowptr + gw);
    const int pe = __ldg(rowptr + gw + 1);

    for (; p + 4 <= pe; p += 4) {
        int n0 = __ldg(end + p), n1 = __ldg(end + p + 1);
        int n2 = __ldg(end + p + 2), n3 = __ldg(end + p + 3);
        float4 w0 = __ldg(ew + p), w1 = __ldg(ew + p + 1);
        float4 w2 = __ldg(ew + p + 2), w3 = __ldg(ew + p + 3);
        float2 x0 = ldx<XHALF>(x, n0, lane);
        float2 x1 = ldx<XHALF>(x, n1, lane);
        float2 x2 = ldx<XHALF>(x, n2, lane);
        float2 x3 = ldx<XHALF>(x, n3, lane);
        a0.x = fmaf(w0.x, x0.x, a0.x); a0.y = fmaf(w0.x, x0.y, a0.y);
        a1.x = fmaf(w0.y, x0.x, a1.x); a1.y = fmaf(w0.y, x0.y, a1.y);
        a2.x = fmaf(w0.z, x0.x, a2.x); a2.y = fmaf(w0.z, x0.y, a2.y);
        a3.x = fmaf(w0.w, x0.x, a3.x); a3.y = fmaf(w0.w, x0.y, a3.y);
        a0.x = fmaf(w1.x, x1.x, a0.x); a0.y = fmaf(w1.x, x1.y, a0.y);
        a1.x = fmaf(w1.y, x1.x, a1.x); a1.y = fmaf(w1.y, x1.y, a1.y);
        a2.x = fmaf(w1.z, x1.x, a2.x); a2.y = fmaf(w1.z, x1.y, a2.y);
        a3.x = fmaf(w1.w, x1.x, a3.x); a3.y = fmaf(w1.w, x1.y, a3.y);
        a0.x = fmaf(w2.x, x2.x, a0.x); a0.y = fmaf(w2.x, x2.y, a0.y);
        a1.x = fmaf(w2.y, x2.x, a1.x); a1.y = fmaf(w2.y, x2.y, a1.y);
        a2.x = fmaf(w2.z, x2.x, a2.x); a2.y = fmaf(w2.z, x2.y, a2.y);
        a3.x = fmaf(w2.w, x2.x, a3.x); a3.y = fmaf(w2.w, x2.y, a3.y);
        a0.x = fmaf(w3.x, x3.x, a0.x); a0.y = fmaf(w3.x, x3.y, a0.y);
        a1.x = fmaf(w3.y, x3.x, a1.x); a1.y = fmaf(w3.y, x3.y, a1.y);
        a2.x = fmaf(w3.z, x3.x, a2.x); a2.y = fmaf(w3.z, x3.y, a2.y);
        a3.x = fmaf(w3.w, x3.x, a3.x); a3.y = fmaf(w3.w, x3.y, a3.y);
    }
    for (; p < pe; p++) {
        int n0 = __ldg(end + p);
        float4 w0 = __ldg(ew + p);
        float2 x0 = ldx<XHALF>(x, n0, lane);
        a0.x = fmaf(w0.x, x0.x, a0.x); a0.y = fmaf(w0.x, x0.y, a0.y);
        a1.x = fmaf(w0.y, x0.x, a1.x); a1.y = fmaf(w0.y, x0.y, a1.y);
        a2.x = fmaf(w0.z, x0.x, a2.x); a2.y = fmaf(w0.z, x0.y, a2.y);
        a3.x = fmaf(w0.w, x0.x, a3.x); a3.y = fmaf(w0.w, x0.y, a3.y);
    }
    __half2* zr = (__half2*)(zout + (size_t)gw * 256);   // k = b*64+d (b-major = V flat)
    zr[lane]      = __float22half2_rn(a0);
    zr[32 + lane] = __float22half2_rn(a1);
    zr[64 + lane] = __float22half2_rn(a2);
    zr[96 + lane] = __float22half2_rn(a3);
}

// ---------------- HMMA projection GEMM: C[n,OUTD] = Z[n,256] @ W[256,OUTD] + bias ----------------
// HOUT selects fp16 vs fp32 output rows.
template <int OUTD, bool RELU, bool HOUT>
__global__ __launch_bounds__(256)
void k_hgemm(const __half* __restrict__ Z, const float* __restrict__ W,
             const float* __restrict__ bias, void* __restrict__ Cv, int nrows) {
    constexpr int LDA = 264;                     // halves
    constexpr int LDB = (OUTD == 64) ? 72 : 40;  // halves
    constexpr int NT = OUTD / 8;                 // n-tiles per warp strip

    extern __shared__ __half sh[];
    __half* As = sh;                  // [128][LDA]
    __half* Bs = sh + 128 * LDA;      // [256][LDB]

    const int t = threadIdx.x;
    const int warp = t >> 5, lane = t & 31;
    const int rowbase = blockIdx.x * 128;

    // stage Z tile (128 x 256 halves, 16B chunks)
    for (int i = t; i < 128 * 32; i += 256) {
        int row = i >> 5, ch = i & 31;
        int gr = rowbase + row;
        float4 v = make_float4(0.f, 0.f, 0.f, 0.f);
        if (gr < nrows) v = *(const float4*)(Z + (size_t)gr * 256 + ch * 8);
        *(float4*)(As + row * LDA + ch * 8) = v;
    }
    // stage W converted to fp16 (256 x OUTD)
    for (int i = t; i < 256 * OUTD / 4; i += 256) {
        int k = i / (OUTD / 4), c4 = i % (OUTD / 4);
        float4 v = *(const float4*)(W + k * OUTD + c4 * 4);
        __half2* d = (__half2*)(Bs + k * LDB + c4 * 4);
        d[0] = __floats2half2_rn(v.x, v.y);
        d[1] = __floats2half2_rn(v.z, v.w);
    }
    __syncthreads();

    float acc[NT][4];
#pragma unroll
    for (int j = 0; j < NT; j++)
#pragma unroll
        for (int c = 0; c < 4; c++) acc[j][c] = 0.f;

    const int wm = warp * 16;
    const uint32_t As32 = smem_u32(As);
    const uint32_t Bs32 = smem_u32(Bs);
    const int arow = wm + (lane & 7) + ((lane >> 3) & 1) * 8;
    const int acol8 = (lane >> 4) * 8;
    const int brow_off = (lane & 7) + ((lane >> 3) & 1) * 8;
    const int bcol8 = (lane >> 4) * 8;

#pragma unroll 4
    for (int kk = 0; kk < 16; kk++) {
        const int k0 = kk * 16;
        uint32_t a0, a1, a2, a3;
        ldsm_x4(a0, a1, a2, a3, As32 + (arow * LDA + k0 + acol8) * 2);
#pragma unroll
        for (int j = 0; j < NT / 2; j++) {
            const int nb0 = j * 16;
            uint32_t b0, b1, b2, b3;
            ldsm_x4_t(b0, b1, b2, b3,
                      Bs32 + ((k0 + brow_off) * LDB + nb0 + bcol8) * 2);
            mma16816(acc[2 * j],     a0, a1, a2, a3, b0, b1);
            mma16816(acc[2 * j + 1], a0, a1, a2, a3, b2, b3);
        }
    }

    // epilogue: bias (+ReLU), direct gmem stores (fp16 or fp32 per HOUT)
    const int r0 = rowbase + wm + lane / 4;
    const int r1 = r0 + 8;
#pragma unroll
    for (int j = 0; j < NT; j++) {
        int nc = j * 8 + (lane % 4) * 2;
        float2 bv = __ldg((const float2*)(bias + nc));
        float2 o0 = make_float2(acc[j][0] + bv.x, acc[j][1] + bv.y);
        float2 o1 = make_float2(acc[j][2] + bv.x, acc[j][3] + bv.y);
        if (RELU) {
            o0.x = fmaxf(o0.x, 0.f); o0.y = fmaxf(o0.y, 0.f);
            o1.x = fmaxf(o1.x, 0.f); o1.y = fmaxf(o1.y, 0.f);
        }
        if (HOUT) {
            __half* C = (__half*)Cv;
            if (r0 < nrows) *(__half2*)(C + (size_t)r0 * OUTD + nc) = __float22half2_rn(o0);
            if (r1 < nrows) *(__half2*)(C + (size_t)r1 * OUTD + nc) = __float22half2_rn(o1);
        } else {
            float* C = (float*)Cv;
            if (r0 < nrows) *(float2*)(C + (size_t)r0 * OUTD + nc) = o0;
            if (r1 < nrows) *(float2*)(C + (size_t)r1 * OUTD + nc) = o1;
        }
    }
}

// ---------------- host launcher ----------------
extern "C" void kernel_launch(void* const* d_in, const int* in_sizes, int n_in,
                              void* d_out, int out_size) {
    const int*   input_nodes = (const int*)d_in[0];
    const int*   src1  = (const int*)d_in[1];
    const int*   dst1  = (const int*)d_in[2];
    const int*   etyp1 = (const int*)d_in[3];
    const float* norm1 = (const float*)d_in[4];
    const int*   src2  = (const int*)d_in[5];
    const int*   dst2  = (const int*)d_in[6];
    const int*   etyp2 = (const int*)d_in[7];
    const float* norm2 = (const float*)d_in[8];
    const float* emb   = (const float*)d_in[9];
    const float* V1    = (const float*)d_in[10];
    const float* comp1 = (const float*)d_in[11];
    const float* b1    = (const float*)d_in[12];
    const float* V2    = (const float*)d_in[13];
    const float* comp2 = (const float*)d_in[14];
    const float* b2    = (const float*)d_in[15];
    float* out = (float*)d_out;

    void* p;
    int *rowptr1, *cursor1, *rowptr2, *cursor2, *bs1, *bs2, *end1, *end2;
    float4 *ew1, *ew2;
    __half *z1, *z2, *h;
    cudaGetSymbolAddress(&p, g_rowptr1); rowptr1 = (int*)p;
    cudaGetSymbolAddress(&p, g_cursor1); cursor1 = (int*)p;
    cudaGetSymbolAddress(&p, g_rowptr2); rowptr2 = (int*)p;
    cudaGetSymbolAddress(&p, g_cursor2); cursor2 = (int*)p;
    cudaGetSymbolAddress(&p, g_bs1);     bs1     = (int*)p;
    cudaGetSymbolAddress(&p, g_bs2);     bs2     = (int*)p;
    cudaGetSymbolAddress(&p, g_end1);    end1    = (int*)p;
    cudaGetSymbolAddress(&p, g_ew1);     ew1     = (float4*)p;
    cudaGetSymbolAddress(&p, g_end2);    end2    = (int*)p;
    cudaGetSymbolAddress(&p, g_ew2);     ew2     = (float4*)p;
    cudaGetSymbolAddress(&p, g_z1);      z1      = (__half*)p;
    cudaGetSymbolAddress(&p, g_h);       h       = (__half*)p;
    cudaGetSymbolAddress(&p, g_z2);      z2      = (__half*)p;

    const int smem1 = (128 * 264 + 256 * 72) * 2;   // 104448 B
    const int smem2 = (128 * 264 + 256 * 40) * 2;   //  88064 B
    cudaFuncSetAttribute(k_hgemm<64, true, true>,
                         cudaFuncAttributeMaxDynamicSharedMemorySize, smem1);
    cudaFuncSetAttribute(k_hgemm<32, false, false>,
                         cudaFuncAttributeMaxDynamicSharedMemorySize, smem2);

    const int nb1 = (N1C + 2047) / 2048;   // 49
    const int nb2 = (N2C + 2047) / 2048;   // 10
    const int gA = (N1C + 255) / 256;      // 391
    const int gB = (N2C + 255) / 256;      // 79

    // --- counting sort by dst + edge packing (both layers) ---
    k_zero<<<(N1C + 256) / 256, 256>>>(cursor1, N1C, cursor2, N2C);
    k_hist<<<(E1C + E2C + 255) / 256, 256>>>(dst1, dst2, cursor1, cursor2);
    k_scan_local2<<<nb1 + nb2, 256>>>(cursor1, rowptr1, bs1, N1C, nb1,
                                      cursor2, rowptr2, bs2, N2C);
    k_scan_bsums2<<<2, 64>>>(bs1, nb1, bs2, nb2);
    k_scan_add2<<<gA + gB, 256>>>(rowptr1, cursor1, bs1, N1C, E1C, gA,
                                  rowptr2, cursor2, bs2, N2C, E2C);
    k_scatter_pack<<<(E1C + E2C + 255) / 256, 256>>>(
        dst1, src1, etyp1, norm1, input_nodes, (const float4*)comp1,
        cursor1, end1, ew1,
        dst2, src2, etyp2, norm2, (const float4*)comp2,
        cursor2, end2, ew2);

    // --- layer 1: aggregate (fp32 emb gathers) -> project (HMMA, fp16 h out) ---
    k_agg<false><<<(N1C * 32 + 255) / 256, 256>>>(rowptr1, end1, ew1, emb, z1, N1C);
    k_hgemm<64, true, true><<<(N1C + 127) / 128, 256, smem1>>>(z1, V1, b1, h, N1C);

    // --- layer 2: aggregate (fp16 L2-resident h gathers) -> project (fp32 out) ---
    k_agg<true><<<(N2C * 32 + 255) / 256, 256>>>(rowptr2, end2, ew2, h, z2, N2C);
    k_hgemm<32, false, false><<<(N2C + 127) / 128, 256, smem2>>>(z2, V2, b2, out, N2C);
}